// round 3
// baseline (speedup 1.0000x reference)
#include <cuda_runtime.h>
#include <cuda_bf16.h>

#define N_CP    128
#define N_DATA  32768
#define BATCH   16
#define TPB     256      // 64 n-threads x 4 batch-groups
#define NTH     64       // n-threads per block (each covers 2 n via float2)
#define BG      4        // batch groups
#define BPG     4        // batches per group
#define CHUNK   16       // float2 loads per phase

// inputs: [0] input [16,3] (UNUSED), [1] control_points [16,3,128],
// [2] weights [16,1,128], [3] N [128,32768] ; output dp [16,3,32768] f32

__global__ __launch_bounds__(TPB) void nurbs_sparse_kernel(
    const float* __restrict__ cp,
    const float* __restrict__ w,
    const float* __restrict__ Nmat,
    float* __restrict__ out)
{
    // s_pack[c][b] = (w, cp0*w, cp1*w, cp2*w)
    __shared__ float4 s_pack[N_CP * BATCH];   // 32 KB

    const int tid = threadIdx.x;

    for (int idx = tid; idx < N_CP * BATCH; idx += TPB) {
        const int c = idx >> 4;
        const int b = idx & 15;
        const float wv = w[b * N_CP + c];
        float4 p;
        p.x = wv;
        p.y = cp[(b * 3 + 0) * N_CP + c] * wv;
        p.z = cp[(b * 3 + 1) * N_CP + c] * wv;
        p.w = cp[(b * 3 + 2) * N_CP + c] * wv;
        s_pack[c * BATCH + b] = p;
    }
    __syncthreads();

    const int nt  = tid & (NTH - 1);          // 0..63  (warp-contiguous)
    const int bg  = tid >> 6;                 // 0..3   (uniform per warp)
    const int b0  = bg * BPG;
    // two consecutive n per thread
    const int n   = blockIdx.x * (NTH * 2) + nt * 2;

    // acc[b][j][v]: j: 0=W,1..3=dims ; v: which of the 2 n
    float acc[BPG][4][2];
    #pragma unroll
    for (int b = 0; b < BPG; b++)
        #pragma unroll
        for (int j = 0; j < 4; j++)
            acc[b][j][0] = acc[b][j][1] = 0.0f;

    const float2* __restrict__ colp =
        (const float2*)(Nmat + n);            // column pointer, stride N_DATA/2 float2

    // Phase-decoupled sparse scan: CHUNK independent float2 LDGs, then
    // branchy FMA pass (band of ~4 nonzero rows, warp-coherent skip).
    #pragma unroll
    for (int ch = 0; ch < N_CP / CHUNK; ch++) {
        float2 nv[CHUNK];
        #pragma unroll
        for (int k = 0; k < CHUNK; k++)
            nv[k] = colp[(size_t)(ch * CHUNK + k) * (N_DATA / 2)];

        #pragma unroll
        for (int k = 0; k < CHUNK; k++) {
            if (nv[k].x != 0.0f || nv[k].y != 0.0f) {
                const int c = ch * CHUNK + k;
                #pragma unroll
                for (int b = 0; b < BPG; b++) {
                    const float4 p = s_pack[c * BATCH + b0 + b]; // warp-uniform
                    acc[b][0][0] = fmaf(p.x, nv[k].x, acc[b][0][0]);
                    acc[b][1][0] = fmaf(p.y, nv[k].x, acc[b][1][0]);
                    acc[b][2][0] = fmaf(p.z, nv[k].x, acc[b][2][0]);
                    acc[b][3][0] = fmaf(p.w, nv[k].x, acc[b][3][0]);
                    acc[b][0][1] = fmaf(p.x, nv[k].y, acc[b][0][1]);
                    acc[b][1][1] = fmaf(p.y, nv[k].y, acc[b][1][1]);
                    acc[b][2][1] = fmaf(p.z, nv[k].y, acc[b][2][1]);
                    acc[b][3][1] = fmaf(p.w, nv[k].y, acc[b][3][1]);
                }
            }
        }
    }

    // Epilogue: divide by W, float2 stores (coalesced within group).
    #pragma unroll
    for (int b = 0; b < BPG; b++) {
        const float inv0 = 1.0f / acc[b][0][0];
        const float inv1 = 1.0f / acc[b][0][1];
        #pragma unroll
        for (int d = 0; d < 3; d++) {
            float2 o;
            o.x = acc[b][d + 1][0] * inv0;
            o.y = acc[b][d + 1][1] * inv1;
            *(float2*)(out + (size_t)((b0 + b) * 3 + d) * N_DATA + n) = o;
        }
    }
}

extern "C" void kernel_launch(void* const* d_in, const int* in_sizes, int n_in,
                              void* d_out, int out_size) {
    const float* cp   = (const float*)d_in[1];
    const float* w    = (const float*)d_in[2];
    const float* Nmat = (const float*)d_in[3];
    float* out = (float*)d_out;

    nurbs_sparse_kernel<<<N_DATA / (NTH * 2), TPB>>>(cp, w, Nmat, out);
}